// round 2
// baseline (speedup 1.0000x reference)
#include <cuda_runtime.h>
#include <mma.h>
#include <math.h>

using namespace nvcuda;

#define T_TOK 2048
#define H_DIM 2048
#define IM_DIM 1024
#define IS_DIM 2048
#define NE 16
#define TOPK 8
#define RSCALE 2.5f

// ---------------- scratch (__device__ globals: allocation-free) ----------------
__device__ int   g_counts[NE];
__device__ int   g_tok[NE * T_TOK];
__device__ float g_wt[NE * T_TOK];
__device__ float g_act[(size_t)NE * T_TOK * IM_DIM];   // routed silu(g)*u, 128 MB
__device__ float g_act_s[(size_t)T_TOK * IS_DIM];      // shared silu(g)*u, 16 MB

// ---------------- router ----------------
__global__ void zero_counts_kernel() {
    if (threadIdx.x < NE) g_counts[threadIdx.x] = 0;
}

__global__ void __launch_bounds__(256) router_kernel(
    const float* __restrict__ hmat, const float* __restrict__ gate_w)
{
    int t = blockIdx.x * (blockDim.x / 32) + (threadIdx.x >> 5);
    int lane = threadIdx.x & 31;
    if (t >= T_TOK) return;
    const float* hr = hmat + (size_t)t * H_DIM;

    float logits[NE];
    #pragma unroll
    for (int e = 0; e < NE; e++) {
        const float* gw = gate_w + e * H_DIM;
        float s = 0.f;
        for (int i = lane; i < H_DIM; i += 32) s += hr[i] * gw[i];
        #pragma unroll
        for (int o = 16; o > 0; o >>= 1) s += __shfl_down_sync(0xffffffff, s, o);
        logits[e] = __shfl_sync(0xffffffff, s, 0);
    }

    if (lane == 0) {
        float w[NE]; bool sel[NE];
        #pragma unroll
        for (int e = 0; e < NE; e++) { w[e] = 1.f / (1.f + expf(-logits[e])); sel[e] = false; }
        int idx[TOPK]; float sum = 0.f;
        #pragma unroll
        for (int r = 0; r < TOPK; r++) {
            int bi = -1; float bv = -1e30f;
            #pragma unroll
            for (int e = 0; e < NE; e++)
                if (!sel[e] && w[e] > bv) { bv = w[e]; bi = e; }
            sel[bi] = true; idx[r] = bi; sum += bv;
        }
        float inv = RSCALE / (sum + 1e-6f);
        #pragma unroll
        for (int r = 0; r < TOPK; r++) {
            int e = idx[r];
            int slot = atomicAdd(&g_counts[e], 1);
            g_tok[e * T_TOK + slot] = t;
            g_wt[e * T_TOK + slot]  = w[e] * inv;
        }
    }
}

// ---------------- fused gate+up+SiLU GEMM (tf32 wmma) ----------------
// C tile 64x64; block 256 thr = 8 warps (4 x 2), each warp 16x32 (2 frags) per matrix.
template<bool SH, int NCOLS>
__global__ void __launch_bounds__(256) gateup_kernel(
    const float* __restrict__ hmat,
    const float* __restrict__ Wgp,
    const float* __restrict__ Wup)
{
    const int e    = SH ? 0 : blockIdx.z;
    const int M    = SH ? T_TOK : g_counts[e];
    const int row0 = blockIdx.y * 64;
    if (row0 >= M) return;
    const int col0 = blockIdx.x * 64;

    const float* Wg = SH ? Wgp : Wgp + (size_t)e * H_DIM * NCOLS;
    const float* Wu = SH ? Wup : Wup + (size_t)e * H_DIM * NCOLS;
    float* actOut   = SH ? g_act_s : g_act + (size_t)e * T_TOK * IM_DIM;

    __shared__ float sA[64 * 40];       // 64 x 32 (+pad)
    __shared__ float sB[2][32 * 72];    // 32 x 64 (+pad) for Wg, Wu
    __shared__ int   sTok[64];

    const int tid = threadIdx.x;
    if (tid < 64) {
        int r = row0 + tid;
        sTok[tid] = (r < M) ? (SH ? r : g_tok[e * T_TOK + r]) : -1;
    }
    __syncthreads();

    const int warp = tid >> 5;
    const int wm = warp & 3, wn = warp >> 2;

    wmma::fragment<wmma::accumulator, 16, 16, 8, float> accg[2], accu[2];
    #pragma unroll
    for (int j = 0; j < 2; j++) { wmma::fill_fragment(accg[j], 0.f); wmma::fill_fragment(accu[j], 0.f); }

    for (int k0 = 0; k0 < H_DIM; k0 += 32) {
        #pragma unroll
        for (int it = 0; it < 8; it++) {
            int li = tid + it * 256;
            int r = li >> 5, c = li & 31;
            int t = sTok[r];
            sA[r * 40 + c] = (t >= 0) ? hmat[(size_t)t * H_DIM + k0 + c] : 0.f;
        }
        #pragma unroll
        for (int it = 0; it < 8; it++) {
            int li = tid + it * 256;
            int r = li >> 6, c = li & 63;
            size_t off = (size_t)(k0 + r) * NCOLS + col0 + c;
            sB[0][r * 72 + c] = Wg[off];
            sB[1][r * 72 + c] = Wu[off];
        }
        __syncthreads();
        #pragma unroll
        for (int kk = 0; kk < 4; kk++) {
            wmma::fragment<wmma::matrix_a, 16, 16, 8, wmma::precision::tf32, wmma::row_major> a;
            wmma::load_matrix_sync(a, &sA[(wm * 16) * 40 + kk * 8], 40);
            #pragma unroll
            for (int i = 0; i < a.num_elements; i++) a.x[i] = wmma::__float_to_tf32(a.x[i]);
            #pragma unroll
            for (int j = 0; j < 2; j++) {
                wmma::fragment<wmma::matrix_b, 16, 16, 8, wmma::precision::tf32, wmma::row_major> b;
                wmma::load_matrix_sync(b, &sB[0][(kk * 8) * 72 + wn * 32 + j * 16], 72);
                #pragma unroll
                for (int i = 0; i < b.num_elements; i++) b.x[i] = wmma::__float_to_tf32(b.x[i]);
                wmma::mma_sync(accg[j], a, b, accg[j]);
                wmma::load_matrix_sync(b, &sB[1][(kk * 8) * 72 + wn * 32 + j * 16], 72);
                #pragma unroll
                for (int i = 0; i < b.num_elements; i++) b.x[i] = wmma::__float_to_tf32(b.x[i]);
                wmma::mma_sync(accu[j], a, b, accu[j]);
            }
        }
        __syncthreads();
    }

    // SiLU(g) * u fused in registers (acc fragments of same shape share layout)
    #pragma unroll
    for (int j = 0; j < 2; j++) {
        #pragma unroll
        for (int i = 0; i < accg[j].num_elements; i++) {
            float g = accg[j].x[i];
            accg[j].x[i] = (g / (1.f + expf(-g))) * accu[j].x[i];
        }
        float* dst = actOut + (size_t)(row0 + wm * 16) * NCOLS + col0 + wn * 32 + j * 16;
        wmma::store_matrix_sync(dst, accg[j], NCOLS, wmma::mem_row_major);
    }
}

// ---------------- down GEMM + weighted scatter ----------------
template<bool SH, int KDIM>
__global__ void __launch_bounds__(256) down_kernel(
    const float* __restrict__ Wdp, float* __restrict__ outp)
{
    const int e    = SH ? 0 : blockIdx.z;
    const int M    = SH ? T_TOK : g_counts[e];
    const int row0 = blockIdx.y * 64;
    if (row0 >= M) return;
    const int col0 = blockIdx.x * 64;

    const float* A = SH ? g_act_s : g_act + (size_t)e * T_TOK * IM_DIM;
    const float* B = SH ? Wdp : Wdp + (size_t)e * KDIM * H_DIM;

    __shared__ float smem[64 * 40 + 32 * 72];  // sA | sB, aliased as sC (64x72) in epilogue
    float* sA = smem;
    float* sB = smem + 64 * 40;
    __shared__ int   sTok[64];
    __shared__ float sW[64];

    const int tid = threadIdx.x;
    if (tid < 64) {
        int r = row0 + tid;
        if (r < M) { sTok[tid] = SH ? r : g_tok[e * T_TOK + r]; sW[tid] = SH ? 1.f : g_wt[e * T_TOK + r]; }
        else       { sTok[tid] = -1; sW[tid] = 0.f; }
    }
    __syncthreads();

    const int warp = tid >> 5;
    const int wm = warp & 3, wn = warp >> 2;

    wmma::fragment<wmma::accumulator, 16, 16, 8, float> acc[2];
    #pragma unroll
    for (int j = 0; j < 2; j++) wmma::fill_fragment(acc[j], 0.f);

    for (int k0 = 0; k0 < KDIM; k0 += 32) {
        #pragma unroll
        for (int it = 0; it < 8; it++) {
            int li = tid + it * 256;
            int r = li >> 5, c = li & 31;
            int rg = row0 + r;
            sA[r * 40 + c] = (rg < M) ? A[(size_t)rg * KDIM + k0 + c] : 0.f;
        }
        #pragma unroll
        for (int it = 0; it < 8; it++) {
            int li = tid + it * 256;
            int r = li >> 6, c = li & 63;
            sB[r * 72 + c] = B[(size_t)(k0 + r) * H_DIM + col0 + c];
        }
        __syncthreads();
        #pragma unroll
        for (int kk = 0; kk < 4; kk++) {
            wmma::fragment<wmma::matrix_a, 16, 16, 8, wmma::precision::tf32, wmma::row_major> a;
            wmma::load_matrix_sync(a, &sA[(wm * 16) * 40 + kk * 8], 40);
            #pragma unroll
            for (int i = 0; i < a.num_elements; i++) a.x[i] = wmma::__float_to_tf32(a.x[i]);
            #pragma unroll
            for (int j = 0; j < 2; j++) {
                wmma::fragment<wmma::matrix_b, 16, 16, 8, wmma::precision::tf32, wmma::row_major> b;
                wmma::load_matrix_sync(b, &sB[(kk * 8) * 72 + wn * 32 + j * 16], 72);
                #pragma unroll
                for (int i = 0; i < b.num_elements; i++) b.x[i] = wmma::__float_to_tf32(b.x[i]);
                wmma::mma_sync(acc[j], a, b, acc[j]);
            }
        }
        __syncthreads();
    }

    // park C tile in smem, then weighted scatter (shared: plain store initializes out)
    float* sC = smem;  // 64 x 72 fits in sA+sB footprint
    #pragma unroll
    for (int j = 0; j < 2; j++)
        wmma::store_matrix_sync(&sC[(wm * 16) * 72 + wn * 32 + j * 16], acc[j], 72, wmma::mem_row_major);
    __syncthreads();

    #pragma unroll
    for (int it = 0; it < 16; it++) {
        int li = tid + it * 256;
        int r = li >> 6, c = li & 63;
        int t = sTok[r];
        if (t >= 0) {
            float v = sC[r * 72 + c] * sW[r];
            if (SH) outp[(size_t)t * H_DIM + col0 + c] = v;
            else    atomicAdd(&outp[(size_t)t * H_DIM + col0 + c], v);
        }
    }
}

// ---------------- launch ----------------
extern "C" void kernel_launch(void* const* d_in, const int* in_sizes, int n_in,
                              void* d_out, int out_size)
{
    const float* h   = (const float*)d_in[0];
    const float* gw  = (const float*)d_in[1];
    const float* Wg  = (const float*)d_in[2];
    const float* Wu  = (const float*)d_in[3];
    const float* Wd  = (const float*)d_in[4];
    const float* sWg = (const float*)d_in[5];
    const float* sWu = (const float*)d_in[6];
    const float* sWd = (const float*)d_in[7];
    float* out = (float*)d_out;

    zero_counts_kernel<<<1, 32>>>();
    router_kernel<<<T_TOK / 8, 256>>>(h, gw);

    // shared expert gate/up + routed gate/up (independent; routed reads g_counts from router)
    gateup_kernel<true,  IS_DIM><<<dim3(IS_DIM / 64, T_TOK / 64, 1),  256>>>(h, sWg, sWu);
    gateup_kernel<false, IM_DIM><<<dim3(IM_DIM / 64, T_TOK / 64, NE), 256>>>(h, Wg, Wu);

    // shared down writes every out element (init), routed down atomically accumulates
    down_kernel<true,  IS_DIM><<<dim3(H_DIM / 64, T_TOK / 64, 1),  256>>>(sWd, out);
    down_kernel<false, IM_DIM><<<dim3(H_DIM / 64, T_TOK / 64, NE), 256>>>(Wd, out);
}

// round 7
// speedup vs baseline: 1.7521x; 1.7521x over previous
#include <cuda_runtime.h>
#include <cstdint>
#include <mma.h>
#include <math.h>

using namespace nvcuda;

#define T_TOK 2048
#define H_DIM 2048
#define IM_DIM 1024
#define IS_DIM 2048
#define NE 16
#define TOPK 8
#define RSCALE 2.5f

// ---------------- scratch (__device__ globals: allocation-free) ----------------
__device__ int   g_counts[NE];
__device__ int   g_tok[NE * T_TOK];
__device__ float g_wt[NE * T_TOK];
__device__ float g_act[(size_t)NE * T_TOK * IM_DIM];   // routed silu(g)*u
__device__ float g_act_s[(size_t)T_TOK * IS_DIM];      // shared silu(g)*u

// ---------------- cp.async helpers ----------------
__device__ __forceinline__ void cp16(float* sdst, const float* gsrc, bool valid) {
    unsigned int sa = (unsigned int)__cvta_generic_to_shared(sdst);
    int sz = valid ? 16 : 0;
    asm volatile("cp.async.cg.shared.global [%0], [%1], 16, %2;\n" :: "r"(sa), "l"(gsrc), "r"(sz));
}
#define CP_COMMIT asm volatile("cp.async.commit_group;\n" ::: "memory")
#define CP_WAIT1  asm volatile("cp.async.wait_group 1;\n" ::: "memory")
#define CP_WAIT0  asm volatile("cp.async.wait_group 0;\n" ::: "memory")

// ---------------- router ----------------
__global__ void zero_counts_kernel() {
    if (threadIdx.x < NE) g_counts[threadIdx.x] = 0;
}

__global__ void __launch_bounds__(256) router_kernel(
    const float* __restrict__ hmat, const float* __restrict__ gate_w)
{
    int t = blockIdx.x * 8 + (threadIdx.x >> 5);
    int lane = threadIdx.x & 31;
    if (t >= T_TOK) return;
    const float4* hr = (const float4*)(hmat + (size_t)t * H_DIM);

    float4 hv[16];
    #pragma unroll
    for (int i = 0; i < 16; i++) hv[i] = hr[lane + i * 32];

    float logits[NE];
    #pragma unroll
    for (int e = 0; e < NE; e++) {
        const float4* gw = (const float4*)(gate_w + e * H_DIM);
        float s = 0.f;
        #pragma unroll
        for (int i = 0; i < 16; i++) {
            float4 g = gw[lane + i * 32];
            s += hv[i].x * g.x + hv[i].y * g.y + hv[i].z * g.z + hv[i].w * g.w;
        }
        #pragma unroll
        for (int o = 16; o > 0; o >>= 1) s += __shfl_down_sync(0xffffffff, s, o);
        logits[e] = __shfl_sync(0xffffffff, s, 0);
    }

    if (lane == 0) {
        float w[NE]; bool sel[NE];
        #pragma unroll
        for (int e = 0; e < NE; e++) { w[e] = 1.f / (1.f + expf(-logits[e])); sel[e] = false; }
        int idx[TOPK]; float sum = 0.f;
        #pragma unroll
        for (int r = 0; r < TOPK; r++) {
            int bi = -1; float bv = -1e30f;
            #pragma unroll
            for (int e = 0; e < NE; e++)
                if (!sel[e] && w[e] > bv) { bv = w[e]; bi = e; }
            sel[bi] = true; idx[r] = bi; sum += bv;
        }
        float inv = RSCALE / (sum + 1e-6f);
        #pragma unroll
        for (int r = 0; r < TOPK; r++) {
            int e = idx[r];
            int slot = atomicAdd(&g_counts[e], 1);
            g_tok[e * T_TOK + slot] = t;
            g_wt[e * T_TOK + slot]  = w[e] * inv;
        }
    }
}

// ---------------- fused gate+up+SiLU GEMM (tf32 wmma, cp.async double-buffer) ----------------
// C tile 128x64; 8 warps (4 M x 2 N), each warp 32x32 per matrix. K-step 32.
#define GU_BUF (128*36 + 2*32*68)   // floats per stage

template<bool SH, int NCOLS>
__global__ void __launch_bounds__(256) gateup_kernel(
    const float* __restrict__ hmat,
    const float* __restrict__ Wgp,
    const float* __restrict__ Wup)
{
    extern __shared__ float dynsmem[];
    const int e    = SH ? 0 : blockIdx.z;
    const int M    = SH ? T_TOK : g_counts[e];
    const int row0 = blockIdx.y * 128;
    if (row0 >= M) return;
    const int col0 = blockIdx.x * 64;

    const float* Wg = SH ? Wgp : Wgp + (size_t)e * H_DIM * NCOLS;
    const float* Wu = SH ? Wup : Wup + (size_t)e * H_DIM * NCOLS;
    float* actOut   = SH ? g_act_s : g_act + (size_t)e * T_TOK * IM_DIM;

    __shared__ int sTok[128];
    const int tid = threadIdx.x;
    if (tid < 128) {
        int r = row0 + tid;
        sTok[tid] = (r < M) ? (SH ? r : g_tok[e * T_TOK + r]) : -1;
    }
    __syncthreads();

    auto load_tiles = [&](int buf, int ks) {
        float* sA = dynsmem + buf * GU_BUF;
        float* sB = sA + 128 * 36;
        const int k0 = ks * 32;
        #pragma unroll
        for (int i = 0; i < 4; i++) {                    // A: 128x32 = 1024 f4
            int f = tid + i * 256;
            int r = f >> 3, c4 = f & 7;
            int t = sTok[r];
            cp16(sA + r * 36 + c4 * 4,
                 hmat + (size_t)(t < 0 ? 0 : t) * H_DIM + k0 + c4 * 4, t >= 0);
        }
        #pragma unroll
        for (int i = 0; i < 4; i++) {                    // Bg+Bu: 2 x 32x64 = 1024 f4
            int f = tid + i * 256;
            int m = f >> 9, rem = f & 511;
            int r = rem >> 4, c4 = rem & 15;
            const float* W = m ? Wu : Wg;
            cp16(sB + m * (32 * 68) + r * 68 + c4 * 4,
                 W + (size_t)(k0 + r) * NCOLS + col0 + c4 * 4, true);
        }
    };

    const int warp = tid >> 5;
    const int wm = warp & 3, wn = warp >> 2;

    wmma::fragment<wmma::accumulator, 16, 16, 8, float> accg[2][2], accu[2][2];
    #pragma unroll
    for (int i = 0; i < 2; i++)
        #pragma unroll
        for (int j = 0; j < 2; j++) { wmma::fill_fragment(accg[i][j], 0.f); wmma::fill_fragment(accu[i][j], 0.f); }

    const int NK = H_DIM / 32;
    load_tiles(0, 0); CP_COMMIT;

    for (int ks = 0; ks < NK; ks++) {
        if (ks + 1 < NK) { load_tiles((ks + 1) & 1, ks + 1); CP_COMMIT; CP_WAIT1; }
        else             { CP_WAIT0; }
        __syncthreads();

        float* sA = dynsmem + (ks & 1) * GU_BUF;
        float* sB = sA + 128 * 36;
        #pragma unroll
        for (int kk = 0; kk < 4; kk++) {
            wmma::fragment<wmma::matrix_a, 16, 16, 8, wmma::precision::tf32, wmma::row_major> a[2];
            #pragma unroll
            for (int i = 0; i < 2; i++) {
                wmma::load_matrix_sync(a[i], sA + (wm * 32 + i * 16) * 36 + kk * 8, 36);
                #pragma unroll
                for (int x = 0; x < a[i].num_elements; x++) a[i].x[x] = wmma::__float_to_tf32(a[i].x[x]);
            }
            #pragma unroll
            for (int j = 0; j < 2; j++) {
                wmma::fragment<wmma::matrix_b, 16, 16, 8, wmma::precision::tf32, wmma::row_major> b;
                wmma::load_matrix_sync(b, sB + (kk * 8) * 68 + wn * 32 + j * 16, 68);
                #pragma unroll
                for (int x = 0; x < b.num_elements; x++) b.x[x] = wmma::__float_to_tf32(b.x[x]);
                #pragma unroll
                for (int i = 0; i < 2; i++) wmma::mma_sync(accg[i][j], a[i], b, accg[i][j]);
                wmma::load_matrix_sync(b, sB + 32 * 68 + (kk * 8) * 68 + wn * 32 + j * 16, 68);
                #pragma unroll
                for (int x = 0; x < b.num_elements; x++) b.x[x] = wmma::__float_to_tf32(b.x[x]);
                #pragma unroll
                for (int i = 0; i < 2; i++) wmma::mma_sync(accu[i][j], a[i], b, accu[i][j]);
            }
        }
        __syncthreads();
    }

    // SiLU(g)*u fused in registers (same-shape acc fragments share layout)
    #pragma unroll
    for (int i = 0; i < 2; i++)
        #pragma unroll
        for (int j = 0; j < 2; j++) {
            #pragma unroll
            for (int x = 0; x < accg[i][j].num_elements; x++) {
                float g = accg[i][j].x[x];
                accg[i][j].x[x] = (g / (1.f + expf(-g))) * accu[i][j].x[x];
            }
            float* dst = actOut + (size_t)(row0 + wm * 32 + i * 16) * NCOLS + col0 + wn * 32 + j * 16;
            wmma::store_matrix_sync(dst, accg[i][j], NCOLS, wmma::mem_row_major);
        }
}

// ---------------- down GEMM + weighted scatter ----------------
#define DN_BUF (128*36 + 32*68)     // floats per stage

template<bool SH, int KDIM>
__global__ void __launch_bounds__(256) down_kernel(
    const float* __restrict__ Wdp, float* __restrict__ outp)
{
    extern __shared__ float dynsmem[];
    const int e    = SH ? 0 : blockIdx.z;
    const int M    = SH ? T_TOK : g_counts[e];
    const int row0 = blockIdx.y * 128;
    if (row0 >= M) return;
    const int col0 = blockIdx.x * 64;

    const float* A = SH ? g_act_s : g_act + (size_t)e * T_TOK * IM_DIM;
    const float* B = SH ? Wdp : Wdp + (size_t)e * KDIM * H_DIM;

    __shared__ int   sTok[128];
    __shared__ float sW[128];
    const int tid = threadIdx.x;
    if (tid < 128) {
        int r = row0 + tid;
        if (r < M) { sTok[tid] = SH ? r : g_tok[e * T_TOK + r]; sW[tid] = SH ? 1.f : g_wt[e * T_TOK + r]; }
        else       { sTok[tid] = -1; sW[tid] = 0.f; }
    }
    __syncthreads();

    auto load_tiles = [&](int buf, int ks) {
        float* sA = dynsmem + buf * DN_BUF;
        float* sB = sA + 128 * 36;
        const int k0 = ks * 32;
        #pragma unroll
        for (int i = 0; i < 4; i++) {                    // A: 128x32 = 1024 f4
            int f = tid + i * 256;
            int r = f >> 3, c4 = f & 7;
            bool v = (row0 + r) < M;
            cp16(sA + r * 36 + c4 * 4,
                 A + (size_t)(v ? row0 + r : 0) * KDIM + k0 + c4 * 4, v);
        }
        #pragma unroll
        for (int i = 0; i < 2; i++) {                    // B: 32x64 = 512 f4
            int f = tid + i * 256;
            int r = f >> 4, c4 = f & 15;
            cp16(sB + r * 68 + c4 * 4,
                 B + (size_t)(k0 + r) * H_DIM + col0 + c4 * 4, true);
        }
    };

    const int warp = tid >> 5;
    const int wm = warp & 3, wn = warp >> 2;

    wmma::fragment<wmma::accumulator, 16, 16, 8, float> acc[2][2];
    #pragma unroll
    for (int i = 0; i < 2; i++)
        #pragma unroll
        for (int j = 0; j < 2; j++) wmma::fill_fragment(acc[i][j], 0.f);

    const int NK = KDIM / 32;
    load_tiles(0, 0); CP_COMMIT;

    for (int ks = 0; ks < NK; ks++) {
        if (ks + 1 < NK) { load_tiles((ks + 1) & 1, ks + 1); CP_COMMIT; CP_WAIT1; }
        else             { CP_WAIT0; }
        __syncthreads();

        float* sA = dynsmem + (ks & 1) * DN_BUF;
        float* sB = sA + 128 * 36;
        #pragma unroll
        for (int kk = 0; kk < 4; kk++) {
            wmma::fragment<wmma::matrix_a, 16, 16, 8, wmma::precision::tf32, wmma::row_major> a[2];
            #pragma unroll
            for (int i = 0; i < 2; i++) {
                wmma::load_matrix_sync(a[i], sA + (wm * 32 + i * 16) * 36 + kk * 8, 36);
                #pragma unroll
                for (int x = 0; x < a[i].num_elements; x++) a[i].x[x] = wmma::__float_to_tf32(a[i].x[x]);
            }
            #pragma unroll
            for (int j = 0; j < 2; j++) {
                wmma::fragment<wmma::matrix_b, 16, 16, 8, wmma::precision::tf32, wmma::row_major> b;
                wmma::load_matrix_sync(b, sB + (kk * 8) * 68 + wn * 32 + j * 16, 68);
                #pragma unroll
                for (int x = 0; x < b.num_elements; x++) b.x[x] = wmma::__float_to_tf32(b.x[x]);
                #pragma unroll
                for (int i = 0; i < 2; i++) wmma::mma_sync(acc[i][j], a[i], b, acc[i][j]);
            }
        }
        __syncthreads();
    }

    // park C tile in smem (reuse pipeline buffers), weighted scatter
    float* sC = dynsmem;   // 128 x 68 fits in 2*DN_BUF
    #pragma unroll
    for (int i = 0; i < 2; i++)
        #pragma unroll
        for (int j = 0; j < 2; j++)
            wmma::store_matrix_sync(sC + (wm * 32 + i * 16) * 68 + wn * 32 + j * 16, acc[i][j], 68, wmma::mem_row_major);
    __syncthreads();

    #pragma unroll
    for (int it = 0; it < 32; it++) {
        int li = tid + it * 256;
        int r = li >> 6, c = li & 63;
        int t = sTok[r];
        if (t >= 0) {
            float v = sC[r * 68 + c] * sW[r];
            if (SH) outp[(size_t)t * H_DIM + col0 + c] = v;
            else    atomicAdd(&outp[(size_t)t * H_DIM + col0 + c], v);
        }
    }
}

// ---------------- launch ----------------
extern "C" void kernel_launch(void* const* d_in, const int* in_sizes, int n_in,
                              void* d_out, int out_size)
{
    const float* h   = (const float*)d_in[0];
    const float* gw  = (const float*)d_in[1];
    const float* Wg  = (const float*)d_in[2];
    const float* Wu  = (const float*)d_in[3];
    const float* Wd  = (const float*)d_in[4];
    const float* sWg = (const float*)d_in[5];
    const float* sWu = (const float*)d_in[6];
    const float* sWd = (const float*)d_in[7];
    float* out = (float*)d_out;

    const int GU_SMEM = 2 * GU_BUF * sizeof(float);   // 71680 B
    const int DN_SMEM = 2 * DN_BUF * sizeof(float);   // 54272 B
    cudaFuncSetAttribute(gateup_kernel<true,  IS_DIM>, cudaFuncAttributeMaxDynamicSharedMemorySize, GU_SMEM);
    cudaFuncSetAttribute(gateup_kernel<false, IM_DIM>, cudaFuncAttributeMaxDynamicSharedMemorySize, GU_SMEM);
    cudaFuncSetAttribute(down_kernel<true,  IS_DIM>,   cudaFuncAttributeMaxDynamicSharedMemorySize, DN_SMEM);
    cudaFuncSetAttribute(down_kernel<false, IM_DIM>,   cudaFuncAttributeMaxDynamicSharedMemorySize, DN_SMEM);

    zero_counts_kernel<<<1, 32>>>();
    router_kernel<<<T_TOK / 8, 256>>>(h, gw);

    gateup_kernel<true,  IS_DIM><<<dim3(IS_DIM / 64, T_TOK / 128, 1),  256, GU_SMEM>>>(h, sWg, sWu);
    gateup_kernel<false, IM_DIM><<<dim3(IM_DIM / 64, T_TOK / 128, NE), 256, GU_SMEM>>>(h, Wg, Wu);

    down_kernel<true,  IS_DIM><<<dim3(H_DIM / 64, T_TOK / 128, 1),  256, DN_SMEM>>>(sWd, out);
    down_kernel<false, IM_DIM><<<dim3(H_DIM / 64, T_TOK / 128, NE), 256, DN_SMEM>>>(Wd, out);
}